// round 16
// baseline (speedup 1.0000x reference)
#include <cuda_runtime.h>
#include <cstdint>

#define NVOX    150000
#define CIN     32
#define COUT    64
#define KCENTER 13
#define NBLK    592                     // 148 SM x 4 resident -> all wave-1
#define NCH16   (NVOX / 16)             // 9375 (exact)
#define SEGV    8192
#define SPK     ((NVOX + SEGV - 1) / SEGV)
#define NSEG    (26 * SPK)              // 494
#define ECAP    4096
#define LCAP    1024
#define FULLM   0xffffffffu
#define NWARPT  (NBLK * 8)              // 4736
#define NJOBS   52                      // 26 k x 2 channel-halves
#define BASESL  (NWARPT / NJOBS)        // 91
#define EXTRASL (NWARPT - NJOBS*BASESL)

typedef unsigned long long ull;

__device__ float    g_stats[2*COUT];
__device__ int      g_ecnt[26];
__device__ int2     g_elist[26*ECAP];
__device__ unsigned g_work[2];          // one steal counter per channel-half
__device__ unsigned g_bar1, g_bar2, g_done;

// ---------------------------------------------------------------- helpers
__device__ __forceinline__ ull pack2(float x, float y) {
    ull r; asm("mov.b64 %0, {%1, %2};" : "=l"(r) : "f"(x), "f"(y)); return r;
}
__device__ __forceinline__ void unpack2(ull v, float& x, float& y) {
    asm("mov.b64 {%0, %1}, %2;" : "=f"(x), "=f"(y) : "l"(v));
}
__device__ __forceinline__ void ffma2(ull& acc, ull a, ull b) {
    asm("fma.rn.f32x2 %0, %1, %2, %0;" : "+l"(acc) : "l"(a), "l"(b));
}
__device__ __forceinline__ uint32_t s2u(const void* p) {
    return (uint32_t)__cvta_generic_to_shared(p);
}
__device__ __forceinline__ void cp16(uint32_t d, const void* s) {
    asm volatile("cp.async.cg.shared.global [%0], [%1], 16;" :: "r"(d), "l"(s));
}
__device__ __forceinline__ void cpcommit() {
    asm volatile("cp.async.commit_group;" ::: "memory");
}
template<int N> __device__ __forceinline__ void cpwaitg() {
    asm volatile("cp.async.wait_group %0;" :: "n"(N) : "memory");
}

extern "C" __global__ void __launch_bounds__(256, 4)
fused_kernel(const float* __restrict__ features,
             const float* __restrict__ weight,
             const float* __restrict__ gamma,
             const float* __restrict__ beta,
             const int*   __restrict__ nbr,
             float* __restrict__ out)
{
    __shared__ float4 sBuf[8][256];      // 32 KB: per-warp double buffer (2x2KB)
    __shared__ int2   sEnt[LCAP];        // 8 KB: phase-A staging
    __shared__ int    sCnt, sBase;
    __shared__ float  sStats[2*COUT];
    __shared__ float  sc[COUT], sh[COUT];

    const int t    = threadIdx.x;
    const int lane = t & 31;
    const int warp = t >> 5;
    const int sub  = warp & 1;           // fixed channel-half for this warp
    const int dD   = sub * 32 + lane;    // dense output channel

    if (t < 2*COUT) sStats[t] = 0.f;

    // ================= phase A: compact per-k extras lists ===================
    for (int seg = blockIdx.x; seg < NSEG; seg += NBLK) {
        int kq = seg / SPK, kk = kq + (kq >= KCENTER);
        int n0 = (seg % SPK) * SEGV;
        if (t == 0) sCnt = 0;
        __syncthreads();
        #pragma unroll 4
        for (int i = 0; i < SEGV; i += 256) {
            int n = n0 + i + t;
            int idx = (n < NVOX) ? __ldg(&nbr[(size_t)kk*NVOX + n]) : -1;
            if (idx >= 0) {
                int p = atomicAdd(&sCnt, 1);
                if (p < LCAP) sEnt[p] = make_int2(n, idx);
            }
        }
        __syncthreads();
        if (t == 0) sBase = atomicAdd(&g_ecnt[kq], min(sCnt, LCAP));
        __syncthreads();
        int cnt = min(sCnt, LCAP), base = sBase;
        for (int e = t; e < cnt; e += 256)
            if (base + e < ECAP) g_elist[kq*ECAP + base + e] = sEnt[e];
        __syncthreads();
    }

    // ================= phase B: dense GEMM, warp-independent, 2-deep pipe =====
    ull wreg[16];                        // one channel: 16 c-pairs = 32 regs
    {
        const float* wk = weight + KCENTER*CIN*COUT + dD;
        #pragma unroll
        for (int c2 = 0; c2 < 16; c2++)
            wreg[c2] = pack2(__ldg(&wk[(2*c2)*COUT]), __ldg(&wk[(2*c2+1)*COUT]));
    }
    float sD = 0.f, qD = 0.f;
    const uint32_t bufA = s2u(&sBuf[warp][0]);

    auto stage16 = [&](int b, int chunk) {
        if (chunk < NCH16) {
            const float4* src = (const float4*)(features + (size_t)chunk * 16 * CIN);
            uint32_t dst = bufA + (uint32_t)b * 2048u;
            #pragma unroll
            for (int j = 0; j < 4; j++)
                cp16(dst + (uint32_t)(j*32 + lane) * 16u, src + j*32 + lane);
        }
        cpcommit();
    };
    auto steal = [&]() -> int {
        int c;
        if (lane == 0) c = (int)atomicAdd(&g_work[sub], 1u);
        return __shfl_sync(FULLM, c, 0);
    };

    int c_cur = steal(); stage16(0, c_cur);
    int c_nxt = steal(); stage16(1, c_nxt);
    int b = 0;
    while (c_cur < NCH16) {
        cpwaitg<1>();                    // buffer b complete
        __syncwarp();
        {
            const int n0 = c_cur * 16;   // exact: no bounds checks needed
            const ulonglong2* F = (const ulonglong2*)(&sBuf[warp][0]) + b*128;
            #pragma unroll
            for (int i = 0; i < 16; i += 4) {
                const ulonglong2* R = F + i*8;
                ull A0=0, A1=0, A2=0, A3=0;
                #pragma unroll
                for (int j = 0; j < 8; j++) {
                    ulonglong2 f0 = R[j], f1 = R[8+j], f2 = R[16+j], f3 = R[24+j];
                    ffma2(A0, f0.x, wreg[2*j]); ffma2(A0, f0.y, wreg[2*j+1]);
                    ffma2(A1, f1.x, wreg[2*j]); ffma2(A1, f1.y, wreg[2*j+1]);
                    ffma2(A2, f2.x, wreg[2*j]); ffma2(A2, f2.y, wreg[2*j+1]);
                    ffma2(A3, f3.x, wreg[2*j]); ffma2(A3, f3.y, wreg[2*j+1]);
                }
                float lo, hi, r0, r1, r2, r3;
                unpack2(A0, lo, hi); r0 = lo + hi;
                unpack2(A1, lo, hi); r1 = lo + hi;
                unpack2(A2, lo, hi); r2 = lo + hi;
                unpack2(A3, lo, hi); r3 = lo + hi;
                out[(size_t)(n0+i  )*COUT + dD] = r0;
                out[(size_t)(n0+i+1)*COUT + dD] = r1;
                out[(size_t)(n0+i+2)*COUT + dD] = r2;
                out[(size_t)(n0+i+3)*COUT + dD] = r3;
                sD += (r0 + r1) + (r2 + r3);
                qD = fmaf(r0, r0, fmaf(r1, r1, fmaf(r2, r2, fmaf(r3, r3, qD))));
            }
        }
        int c_new = steal();             // atomic latency overlaps next compute
        stage16(b, c_new);               // refill the buffer just consumed
        c_cur = c_nxt; c_nxt = c_new; b ^= 1;
    }
    cpwaitg<0>();

    // ---------------- grid barrier 1 (lists + dense out complete) ------------
    __threadfence();
    __syncthreads();
    if (t == 0) {
        atomicAdd(&g_bar1, 1u);
        while (*(volatile unsigned*)&g_bar1 < (unsigned)NBLK) __nanosleep(64);
    }
    __syncthreads();
    __threadfence();

    // ================= phase C: extras (k x channel-half jobs) ================
    float sE = 0.f, qE = 0.f;
    int   dE = lane;
    {
        const int ew    = blockIdx.x*8 + warp;
        const int jc    = ew % NJOBS;
        const int slice = ew / NJOBS;
        const int NS    = BASESL + (jc < EXTRASL ? 1 : 0);
        const int kq    = jc >> 1;
        dE = (jc & 1)*32 + lane;
        const int cnt = min(g_ecnt[kq], ECAP);
        if (slice < NS && slice < cnt) {
            const int kk = kq + (kq >= KCENTER);
            const float* wk = weight + kk*CIN*COUT + dE;
            #pragma unroll
            for (int c2 = 0; c2 < 16; c2++)
                wreg[c2] = pack2(__ldg(&wk[(2*c2)*COUT]), __ldg(&wk[(2*c2+1)*COUT]));
            const int2* lst = g_elist + kq*ECAP;
            for (int e = slice; e < cnt; e += NS) {
                int2 en = __ldg(&lst[e]);
                const ulonglong2* Fr = (const ulonglong2*)(features + (size_t)en.y*CIN);
                ull A = 0, B = 0;
                #pragma unroll
                for (int j = 0; j < 8; j++) {
                    ulonglong2 u = Fr[j];
                    ffma2(A, u.x, wreg[2*j]);
                    ffma2(B, u.y, wreg[2*j+1]);
                }
                float lo, hi, l2, h2;
                unpack2(A, lo, hi); unpack2(B, l2, h2);
                float r = (lo + hi) + (l2 + h2);
                float old = atomicAdd(&out[(size_t)en.x*COUT + dE], r);
                sE += r;
                qE = fmaf(r, old + old + r, qE);
            }
        }
    }

    // ---------------- block stats reduce ------------------------------------
    atomicAdd(&sStats[dD], sD);
    atomicAdd(&sStats[COUT + dD], qD);
    if (sE != 0.f || qE != 0.f) {
        atomicAdd(&sStats[dE], sE);
        atomicAdd(&sStats[COUT + dE], qE);
    }
    __syncthreads();
    if (t < 2*COUT) atomicAdd(&g_stats[t], sStats[t]);

    // ---------------- grid barrier 2 -----------------------------------------
    __threadfence();
    __syncthreads();
    if (t == 0) {
        atomicAdd(&g_bar2, 1u);
        while (*(volatile unsigned*)&g_bar2 < (unsigned)NBLK) __nanosleep(64);
    }
    __syncthreads();
    __threadfence();

    // ================= phase D: finalize + normalize (L2-hot) ================
    if (t < COUT) {
        float inv_n = 1.0f / (float)NVOX;
        float mean  = g_stats[t] * inv_n;
        float var   = g_stats[COUT + t] * inv_n - mean*mean;
        float inv   = rsqrtf(var + 1e-5f);
        float scl   = gamma[t] * inv;
        sc[t] = scl;
        sh[t] = beta[t] - mean*scl;
    }
    __syncthreads();

    {
        const int total4 = NVOX*COUT/4;
        float4* o4 = (float4*)out;
        for (int i = blockIdx.x*256 + t; i < total4; i += NBLK*256) {
            float4 v = o4[i];
            int bd = (i*4) & (COUT-1);
            v.x = fmaxf(fmaf(v.x, sc[bd+0], sh[bd+0]), 0.f);
            v.y = fmaxf(fmaf(v.y, sc[bd+1], sh[bd+1]), 0.f);
            v.z = fmaxf(fmaf(v.z, sc[bd+2], sh[bd+2]), 0.f);
            v.w = fmaxf(fmaf(v.w, sc[bd+3], sh[bd+3]), 0.f);
            o4[i] = v;
        }
    }

    // ---------------- reset for next graph replay -----------------------------
    __syncthreads();
    if (t == 0) {
        unsigned d = atomicAdd(&g_done, 1u);
        if (d == (unsigned)NBLK - 1u) {
            #pragma unroll
            for (int i = 0; i < 2*COUT; i++) g_stats[i] = 0.f;
            #pragma unroll
            for (int i = 0; i < 26; i++) g_ecnt[i] = 0;
            __threadfence();
            g_work[0] = 0u; g_work[1] = 0u;
            g_bar1 = 0u; g_bar2 = 0u; g_done = 0u;
            __threadfence();
        }
    }
}

// ---------------------------------------------------------------- launch
extern "C" void kernel_launch(void* const* d_in, const int* in_sizes, int n_in,
                              void* d_out, int out_size)
{
    const float* features = (const float*)d_in[0];  // [150000,32]
    const float* weight   = (const float*)d_in[1];  // [27,32,64]
    const float* gamma    = (const float*)d_in[2];  // [64]
    const float* beta     = (const float*)d_in[3];  // [64]
    const int*   nbr      = (const int*)  d_in[4];  // [27,150000]
    float* out = (float*)d_out;                     // [150000,64]

    fused_kernel<<<NBLK, 256>>>(features, weight, gamma, beta, nbr, out);
}

// round 17
// speedup vs baseline: 1.0689x; 1.0689x over previous
#include <cuda_runtime.h>
#include <cstdint>

#define NVOX    150000
#define CIN     32
#define COUT    64
#define KCENTER 13
#define NBLK    444                     // 148 SM x 3 resident -> all wave-1
#define NCH     ((NVOX + 31) / 32)      // 4688
#define SEGV    8192
#define SPK     ((NVOX + SEGV - 1) / SEGV)
#define NSEG    (26 * SPK)              // 494
#define ECAP    4096
#define LCAP    1024
#define FULLM   0xffffffffu
#define NWARPT  (NBLK * 8)              // 3552
#define NJOBS   52                      // 26 k x 2 channel-halves
#define BASESL  (NWARPT / NJOBS)        // 68
#define EXTRASL (NWARPT - NJOBS*BASESL)

typedef unsigned long long ull;

__device__ float    g_stats[2*COUT];
__device__ int      g_ecnt[26];
__device__ int2     g_elist[26*ECAP];
__device__ unsigned g_work, g_workA, g_bar1, g_bar2, g_done;

// ---------------------------------------------------------------- helpers
__device__ __forceinline__ ull pack2(float x, float y) {
    ull r; asm("mov.b64 %0, {%1, %2};" : "=l"(r) : "f"(x), "f"(y)); return r;
}
__device__ __forceinline__ void unpack2(ull v, float& x, float& y) {
    asm("mov.b64 {%0, %1}, %2;" : "=f"(x), "=f"(y) : "l"(v));
}
__device__ __forceinline__ void ffma2(ull& acc, ull a, ull b) {
    asm("fma.rn.f32x2 %0, %1, %2, %0;" : "+l"(acc) : "l"(a), "l"(b));
}
__device__ __forceinline__ uint32_t s2u(const void* p) {
    return (uint32_t)__cvta_generic_to_shared(p);
}
__device__ __forceinline__ void cp16(uint32_t d, const void* s) {
    asm volatile("cp.async.cg.shared.global [%0], [%1], 16;" :: "r"(d), "l"(s));
}
__device__ __forceinline__ void cpwait0() {
    asm volatile("cp.async.commit_group;\ncp.async.wait_group 0;" ::: "memory");
}
__device__ __forceinline__ void barpair(int id) {
    asm volatile("bar.sync %0, 64;" :: "r"(id) : "memory");
}

extern "C" __global__ void __launch_bounds__(256, 3)
fused_kernel(const float* __restrict__ features,
             const float* __restrict__ weight,
             const float* __restrict__ gamma,
             const float* __restrict__ beta,
             const int*   __restrict__ nbr,
             float* __restrict__ out)
{
    __shared__ float4 sBuf[4][256];      // 16 KB: one 32-row tile per warp pair
    __shared__ int2   sEnt[LCAP];        // 8 KB: phase-A staging
    __shared__ int    sCh[4];
    __shared__ int    sCnt, sBase, sSeg;
    __shared__ float  sStats[2*COUT];
    __shared__ float  sc[COUT], sh[COUT];

    const int t    = threadIdx.x;
    const int lane = t & 31;
    const int warp = t >> 5;
    const int pair = warp >> 1;
    const int sub  = warp & 1;
    const int dD   = sub * 32 + lane;    // this lane's dense output channel

    if (t < 2*COUT) sStats[t] = 0.f;

    // ================= phase A: compact per-k extras lists (work-stolen) =====
    for (;;) {
        __syncthreads();
        if (t == 0) { sSeg = (int)atomicAdd(&g_workA, 1u); sCnt = 0; }
        __syncthreads();
        const int seg = sSeg;
        if (seg >= NSEG) break;
        int kq = seg / SPK, kk = kq + (kq >= KCENTER);
        int n0 = (seg % SPK) * SEGV;
        #pragma unroll 4
        for (int i = 0; i < SEGV; i += 256) {
            int n = n0 + i + t;
            int idx = (n < NVOX) ? __ldg(&nbr[(size_t)kk*NVOX + n]) : -1;
            if (idx >= 0) {
                int p = atomicAdd(&sCnt, 1);
                if (p < LCAP) sEnt[p] = make_int2(n, idx);
            }
        }
        __syncthreads();
        if (t == 0) sBase = atomicAdd(&g_ecnt[kq], min(sCnt, LCAP));
        __syncthreads();
        int cnt = min(sCnt, LCAP), base = sBase;
        for (int e = t; e < cnt; e += 256)
            if (base + e < ECAP) g_elist[kq*ECAP + base + e] = sEnt[e];
    }

    // ================= phase B: dense center GEMM ============================
    // weights for ONE channel: 16 c-pairs = 32 regs
    ull wreg[16];
    {
        const float* wk = weight + KCENTER*CIN*COUT + dD;
        #pragma unroll
        for (int c2 = 0; c2 < 16; c2++)
            wreg[c2] = pack2(__ldg(&wk[(2*c2)*COUT]), __ldg(&wk[(2*c2+1)*COUT]));
    }
    float sD = 0.f, qD = 0.f;

    for (;;) {
        if (sub == 0 && lane == 0) sCh[pair] = (int)atomicAdd(&g_work, 1u);
        barpair(1 + pair);
        const int chunk = sCh[pair];
        if (chunk >= NCH) break;
        const int n0 = chunk * 32;
        const int nv = min(32, NVOX - n0);

        // each warp of the pair stages 16 rows (4 cp.async.16B per lane)
        {
            const float4* src = (const float4*)(features + (size_t)n0 * CIN);
            uint32_t dst = s2u(&sBuf[pair][0]);
            #pragma unroll
            for (int j = 0; j < 4; j++) {
                int e = sub*128 + j*32 + lane;
                if ((e >> 3) < nv) cp16(dst + e*16, src + e);
            }
        }
        cpwait0();
        barpair(1 + pair);

        const ulonglong2* F = (const ulonglong2*)&sBuf[pair][0];
        for (int i = 0; i < nv; i += 4) {
            const ulonglong2* R = F + i*8;
            ull A0=0, A1=0, A2=0, A3=0;
            #pragma unroll
            for (int j = 0; j < 8; j++) {
                ulonglong2 f0 = R[j], f1 = R[8+j], f2 = R[16+j], f3 = R[24+j];
                ffma2(A0, f0.x, wreg[2*j]); ffma2(A0, f0.y, wreg[2*j+1]);
                ffma2(A1, f1.x, wreg[2*j]); ffma2(A1, f1.y, wreg[2*j+1]);
                ffma2(A2, f2.x, wreg[2*j]); ffma2(A2, f2.y, wreg[2*j+1]);
                ffma2(A3, f3.x, wreg[2*j]); ffma2(A3, f3.y, wreg[2*j+1]);
            }
            float lo, hi, r0, r1, r2, r3;
            unpack2(A0, lo, hi); r0 = lo + hi;
            unpack2(A1, lo, hi); r1 = lo + hi;
            unpack2(A2, lo, hi); r2 = lo + hi;
            unpack2(A3, lo, hi); r3 = lo + hi;
            out[(size_t)(n0+i  )*COUT + dD] = r0;
            out[(size_t)(n0+i+1)*COUT + dD] = r1;
            out[(size_t)(n0+i+2)*COUT + dD] = r2;
            out[(size_t)(n0+i+3)*COUT + dD] = r3;
            sD += (r0 + r1) + (r2 + r3);
            qD = fmaf(r0, r0, fmaf(r1, r1, fmaf(r2, r2, fmaf(r3, r3, qD))));
        }
        barpair(1 + pair);    // buffer reuse guard
    }

    // ---------------- grid barrier 1 (lists + dense out complete) ------------
    __threadfence();
    __syncthreads();
    if (t == 0) {
        atomicAdd(&g_bar1, 1u);
        while (*(volatile unsigned*)&g_bar1 < (unsigned)NBLK) __nanosleep(64);
    }
    __syncthreads();
    __threadfence();

    // ================= phase C: extras (k x channel-half jobs), 4-way MLP ====
    float sE = 0.f, qE = 0.f;
    int   dE = lane;
    {
        const int ew    = blockIdx.x*8 + warp;
        const int jc    = ew % NJOBS;
        const int slice = ew / NJOBS;
        const int NS    = BASESL + (jc < EXTRASL ? 1 : 0);
        const int kq    = jc >> 1;
        dE = (jc & 1)*32 + lane;
        const int cnt = min(g_ecnt[kq], ECAP);
        if (slice < NS) {
            const int kk = kq + (kq >= KCENTER);
            const float* wke = weight + kk*CIN*COUT + dE;
            #pragma unroll
            for (int c2 = 0; c2 < 16; c2++)
                wreg[c2] = pack2(__ldg(&wke[(2*c2)*COUT]), __ldg(&wke[(2*c2+1)*COUT]));
            const int2* lst = g_elist + kq*ECAP;

            int e = slice;
            for (; e + 3*NS < cnt; e += 4*NS) {
                int2 E0 = __ldg(&lst[e]);
                int2 E1 = __ldg(&lst[e +   NS]);
                int2 E2 = __ldg(&lst[e + 2*NS]);
                int2 E3 = __ldg(&lst[e + 3*NS]);
                const ulonglong2* F0 = (const ulonglong2*)(features + (size_t)E0.y*CIN);
                const ulonglong2* F1 = (const ulonglong2*)(features + (size_t)E1.y*CIN);
                const ulonglong2* F2 = (const ulonglong2*)(features + (size_t)E2.y*CIN);
                const ulonglong2* F3 = (const ulonglong2*)(features + (size_t)E3.y*CIN);
                ull A0=0,B0=0,A1=0,B1=0,A2=0,B2=0,A3=0,B3=0;
                #pragma unroll
                for (int j = 0; j < 8; j++) {
                    ulonglong2 u0 = F0[j], u1 = F1[j], u2 = F2[j], u3 = F3[j];
                    ffma2(A0, u0.x, wreg[2*j]); ffma2(B0, u0.y, wreg[2*j+1]);
                    ffma2(A1, u1.x, wreg[2*j]); ffma2(B1, u1.y, wreg[2*j+1]);
                    ffma2(A2, u2.x, wreg[2*j]); ffma2(B2, u2.y, wreg[2*j+1]);
                    ffma2(A3, u3.x, wreg[2*j]); ffma2(B3, u3.y, wreg[2*j+1]);
                }
                float lo, hi, l2, h2, r, old;
                unpack2(A0, lo, hi); unpack2(B0, l2, h2); r = (lo+hi)+(l2+h2);
                old = atomicAdd(&out[(size_t)E0.x*COUT + dE], r);
                sE += r; qE = fmaf(r, old + old + r, qE);
                unpack2(A1, lo, hi); unpack2(B1, l2, h2); r = (lo+hi)+(l2+h2);
                old = atomicAdd(&out[(size_t)E1.x*COUT + dE], r);
                sE += r; qE = fmaf(r, old + old + r, qE);
                unpack2(A2, lo, hi); unpack2(B2, l2, h2); r = (lo+hi)+(l2+h2);
                old = atomicAdd(&out[(size_t)E2.x*COUT + dE], r);
                sE += r; qE = fmaf(r, old + old + r, qE);
                unpack2(A3, lo, hi); unpack2(B3, l2, h2); r = (lo+hi)+(l2+h2);
                old = atomicAdd(&out[(size_t)E3.x*COUT + dE], r);
                sE += r; qE = fmaf(r, old + old + r, qE);
            }
            for (; e < cnt; e += NS) {
                int2 E0 = __ldg(&lst[e]);
                const ulonglong2* F0 = (const ulonglong2*)(features + (size_t)E0.y*CIN);
                ull A0=0, B0=0;
                #pragma unroll
                for (int j = 0; j < 8; j++) {
                    ulonglong2 u0 = F0[j];
                    ffma2(A0, u0.x, wreg[2*j]); ffma2(B0, u0.y, wreg[2*j+1]);
                }
                float lo, hi, l2, h2;
                unpack2(A0, lo, hi); unpack2(B0, l2, h2);
                float r = (lo+hi)+(l2+h2);
                float old = atomicAdd(&out[(size_t)E0.x*COUT + dE], r);
                sE += r; qE = fmaf(r, old + old + r, qE);
            }
        }
    }

    // ---------------- block stats reduce ------------------------------------
    atomicAdd(&sStats[dD], sD);
    atomicAdd(&sStats[COUT + dD], qD);
    if (sE != 0.f || qE != 0.f) {
        atomicAdd(&sStats[dE], sE);
        atomicAdd(&sStats[COUT + dE], qE);
    }
    __syncthreads();
    if (t < 2*COUT) atomicAdd(&g_stats[t], sStats[t]);

    // ---------------- grid barrier 2 -----------------------------------------
    __threadfence();
    __syncthreads();
    if (t == 0) {
        atomicAdd(&g_bar2, 1u);
        while (*(volatile unsigned*)&g_bar2 < (unsigned)NBLK) __nanosleep(64);
    }
    __syncthreads();
    __threadfence();

    // ================= phase D: finalize + normalize (L2-hot) ================
    if (t < COUT) {
        float inv_n = 1.0f / (float)NVOX;
        float mean  = g_stats[t] * inv_n;
        float var   = g_stats[COUT + t] * inv_n - mean*mean;
        float inv   = rsqrtf(var + 1e-5f);
        float scl   = gamma[t] * inv;
        sc[t] = scl;
        sh[t] = beta[t] - mean*scl;
    }
    __syncthreads();

    {
        const int total4 = NVOX*COUT/4;
        float4* o4 = (float4*)out;
        for (int i = blockIdx.x*256 + t; i < total4; i += NBLK*256) {
            float4 v = o4[i];
            int bd = (i*4) & (COUT-1);
            v.x = fmaxf(fmaf(v.x, sc[bd+0], sh[bd+0]), 0.f);
            v.y = fmaxf(fmaf(v.y, sc[bd+1], sh[bd+1]), 0.f);
            v.z = fmaxf(fmaf(v.z, sc[bd+2], sh[bd+2]), 0.f);
            v.w = fmaxf(fmaf(v.w, sc[bd+3], sh[bd+3]), 0.f);
            o4[i] = v;
        }
    }

    // ---------------- reset for next graph replay -----------------------------
    __syncthreads();
    if (t == 0) {
        unsigned d = atomicAdd(&g_done, 1u);
        if (d == (unsigned)NBLK - 1u) {
            #pragma unroll
            for (int i = 0; i < 2*COUT; i++) g_stats[i] = 0.f;
            #pragma unroll
            for (int i = 0; i < 26; i++) g_ecnt[i] = 0;
            __threadfence();
            g_work = 0u; g_workA = 0u; g_bar1 = 0u; g_bar2 = 0u; g_done = 0u;
            __threadfence();
        }
    }
}

// ---------------------------------------------------------------- launch
extern "C" void kernel_launch(void* const* d_in, const int* in_sizes, int n_in,
                              void* d_out, int out_size)
{
    const float* features = (const float*)d_in[0];  // [150000,32]
    const float* weight   = (const float*)d_in[1];  // [27,32,64]
    const float* gamma    = (const float*)d_in[2];  // [64]
    const float* beta     = (const float*)d_in[3];  // [64]
    const int*   nbr      = (const int*)  d_in[4];  // [27,150000]
    float* out = (float*)d_out;                     // [150000,64]

    fused_kernel<<<NBLK, 256>>>(features, weight, gamma, beta, nbr, out);
}